// round 12
// baseline (speedup 1.0000x reference)
#include <cuda_runtime.h>
#include <cuda_bf16.h>
#include <cstdint>
#include <math.h>

#define S_LEN 4096
#define BATCH 64
#define HSZ   256
#define MROWS (BATCH * S_LEN)   // 262144

typedef unsigned long long ull;

// ---------------- device scratch (allocation-free rule) ----------------
__device__ float g_x [(size_t)MROWS * 128];           // x
__device__ float g_u [(size_t)MROWS * 128];           // tanh(s@Wef1+bef1)
__device__ float g_xw[(size_t)MROWS * 1024];          // [b][s][4HS] (bias baked in)
__device__ float g_j [(size_t)MROWS * HSZ];           // [b][s][HS]
__device__ float g_h [BATCH * HSZ];                   // final h

// fast activations: MUFU-based, saturate correctly at +-inf
__device__ __forceinline__ float sigf(float x) {
    return __fdividef(1.0f, 1.0f + __expf(-x));
}
__device__ __forceinline__ float tanhfast(float x) {
    return 1.0f - __fdividef(2.0f, __expf(2.0f * x) + 1.0f);
}

__device__ __forceinline__ uint32_t s2u(const void* p) {
    uint32_t r;
    asm("{ .reg .u64 t; cvta.to.shared.u64 t, %1; cvt.u32.u64 %0, t; }"
        : "=r"(r) : "l"(p));
    return r;
}

#define FMA2(d, a, b) \
    asm("fma.rn.f32x2 %0, %1, %2, %0;" : "+l"(d) : "l"(a), "l"(b))
#define PACK2(d, a) \
    asm("mov.b64 %0, {%1, %1};" : "=l"(d) : "f"(a))

// ---------------- fused embeddings + event-filter stage 1 ------------------
// s = ev@Ve ; x = s + 2*(vc@Vc + tanh(vn@Vn)) ; u = tanh(s@Wef1 + bef1)
__global__ void __launch_bounds__(256, 1)
k_embed_u(const float* __restrict__ ev, const float* __restrict__ vc,
          const float* __restrict__ vn, const float* __restrict__ Ve,
          const float* __restrict__ Vc, const float* __restrict__ Vn,
          const float* __restrict__ Wef1, const float* __restrict__ bef1) {
    extern __shared__ float sm[];
    float* wE  = sm;                 // [64][128]  -> Wef1 later
    float* wC  = sm + 8192;          // [32][128]
    float* wN  = sm + 12288;         // [16][128]
    float* ie  = sm + 16384;         // [32][64]
    float* ic  = ie + 2048;          // [32][32]
    float* inn = ic + 1024;          // [32][16]
    float* st  = sm + 19968;         // s-tile [32][128]
    int tid = threadIdx.x;
    size_t rb = (size_t)blockIdx.x * 32;

    for (int i = tid; i < 2048; i += 256) ((float4*)wE)[i]  = ((const float4*)Ve)[i];
    for (int i = tid; i < 1024; i += 256) ((float4*)wC)[i]  = ((const float4*)Vc)[i];
    for (int i = tid; i < 512;  i += 256) ((float4*)wN)[i]  = ((const float4*)Vn)[i];
    for (int i = tid; i < 512;  i += 256) ((float4*)ie)[i]  = ((const float4*)(ev + rb * 64))[i];
    for (int i = tid; i < 256;  i += 256) ((float4*)ic)[i]  = ((const float4*)(vc + rb * 32))[i];
    for (int i = tid; i < 128;  i += 256) ((float4*)inn)[i] = ((const float4*)(vn + rb * 16))[i];
    __syncthreads();

    int ty = tid >> 4, tx = tid & 15;
    float sa[2][8], ta[2][8], xa[2][8];
    #pragma unroll
    for (int r = 0; r < 2; r++)
        #pragma unroll
        for (int j = 0; j < 8; j++) { sa[r][j] = 0.f; ta[r][j] = 0.f; }

    #pragma unroll 4
    for (int k = 0; k < 64; k++) {
        float a0 = ie[(ty * 2) * 64 + k], a1 = ie[(ty * 2 + 1) * 64 + k];
        const float* wr = wE + k * 128 + tx * 8;
        float4 w0 = *(const float4*)wr, w1 = *(const float4*)(wr + 4);
        float w[8] = {w0.x, w0.y, w0.z, w0.w, w1.x, w1.y, w1.z, w1.w};
        #pragma unroll
        for (int j = 0; j < 8; j++) { sa[0][j] += a0 * w[j]; sa[1][j] += a1 * w[j]; }
    }
    #pragma unroll 4
    for (int k = 0; k < 32; k++) {
        float a0 = ic[(ty * 2) * 32 + k], a1 = ic[(ty * 2 + 1) * 32 + k];
        const float* wr = wC + k * 128 + tx * 8;
        float4 w0 = *(const float4*)wr, w1 = *(const float4*)(wr + 4);
        float w[8] = {w0.x, w0.y, w0.z, w0.w, w1.x, w1.y, w1.z, w1.w};
        #pragma unroll
        for (int j = 0; j < 8; j++) { ta[0][j] += a0 * w[j]; ta[1][j] += a1 * w[j]; }
    }
    #pragma unroll
    for (int r = 0; r < 2; r++)
        #pragma unroll
        for (int j = 0; j < 8; j++) { xa[r][j] = 2.f * ta[r][j]; ta[r][j] = 0.f; }
    #pragma unroll 4
    for (int k = 0; k < 16; k++) {
        float a0 = inn[(ty * 2) * 16 + k], a1 = inn[(ty * 2 + 1) * 16 + k];
        const float* wr = wN + k * 128 + tx * 8;
        float4 w0 = *(const float4*)wr, w1 = *(const float4*)(wr + 4);
        float w[8] = {w0.x, w0.y, w0.z, w0.w, w1.x, w1.y, w1.z, w1.w};
        #pragma unroll
        for (int j = 0; j < 8; j++) { ta[0][j] += a0 * w[j]; ta[1][j] += a1 * w[j]; }
    }
    #pragma unroll
    for (int r = 0; r < 2; r++) {
        int row = ty * 2 + r;
        size_t grow = rb + row;
        float o[8];
        #pragma unroll
        for (int j = 0; j < 8; j++) o[j] = sa[r][j] + xa[r][j] + 2.f * tanhfast(ta[r][j]);
        float* xp = g_x + grow * 128 + tx * 8;
        *(float4*)xp       = make_float4(o[0], o[1], o[2], o[3]);
        *(float4*)(xp + 4) = make_float4(o[4], o[5], o[6], o[7]);
        float* sp = st + row * 128 + tx * 8;
        *(float4*)sp       = make_float4(sa[r][0], sa[r][1], sa[r][2], sa[r][3]);
        *(float4*)(sp + 4) = make_float4(sa[r][4], sa[r][5], sa[r][6], sa[r][7]);
    }
    __syncthreads();

    for (int i = tid; i < 4096; i += 256) ((float4*)wE)[i] = ((const float4*)Wef1)[i];
    __syncthreads();

    float ua[2][8];
    #pragma unroll
    for (int r = 0; r < 2; r++)
        #pragma unroll
        for (int j = 0; j < 8; j++) ua[r][j] = 0.f;
    #pragma unroll 4
    for (int k = 0; k < 128; k++) {
        float a0 = st[(ty * 2) * 128 + k], a1 = st[(ty * 2 + 1) * 128 + k];
        const float* wr = wE + k * 128 + tx * 8;
        float4 w0 = *(const float4*)wr, w1 = *(const float4*)(wr + 4);
        float w[8] = {w0.x, w0.y, w0.z, w0.w, w1.x, w1.y, w1.z, w1.w};
        #pragma unroll
        for (int j = 0; j < 8; j++) { ua[0][j] += a0 * w[j]; ua[1][j] += a1 * w[j]; }
    }
    float4 b0 = *(const float4*)&bef1[tx * 8];
    float4 b1 = *(const float4*)&bef1[tx * 8 + 4];
    float bb[8] = {b0.x, b0.y, b0.z, b0.w, b1.x, b1.y, b1.z, b1.w};
    #pragma unroll
    for (int r = 0; r < 2; r++) {
        size_t grow = rb + ty * 2 + r;
        float o[8];
        #pragma unroll
        for (int j = 0; j < 8; j++) o[j] = tanhfast(ua[r][j] + bb[j]);
        float* up = g_u + grow * 128 + tx * 8;
        *(float4*)up       = make_float4(o[0], o[1], o[2], o[3]);
        *(float4*)(up + 4) = make_float4(o[4], o[5], o[6], o[7]);
    }
}

// ---------------- K=128 GEMM, 64x128 tile (f32x2): out = act(A@W + b) ------
// 256 threads = 16x16; thread = 4 rows x 8 cols (two 4-col blocks at tx*4 and
// 64+tx*4 for conflict-free Ws reads).
__global__ void __launch_bounds__(256)
k_gemm(const float* __restrict__ A, const float* __restrict__ W,
       const float* __restrict__ bias, float* __restrict__ out,
       int N, int act) {
    extern __shared__ float sm[];
    float* As = sm;            // [64][128]   32 KB
    float* Ws = sm + 8192;     // [128][128]  64 KB
    int tid = threadIdx.x;
    const float4* A4 = (const float4*)A;
    const float4* W4 = (const float4*)W;
    for (int i = tid; i < 2048; i += 256)
        ((float4*)As)[i] = A4[((size_t)blockIdx.x * 64 + (i >> 5)) * 32 + (i & 31)];
    for (int i = tid; i < 4096; i += 256)
        ((float4*)Ws)[i] = W4[(size_t)(i >> 5) * (N >> 2) + blockIdx.y * 32 + (i & 31)];
    __syncthreads();

    int ty = tid >> 4, tx = tid & 15;
    int r0 = ty * 4, cA = tx * 4, cB = 64 + tx * 4;
    ull acc[4][4];   // [row][blkA lo/hi, blkB lo/hi]
    #pragma unroll
    for (int r = 0; r < 4; r++)
        #pragma unroll
        for (int c = 0; c < 4; c++) acc[r][c] = 0ull;

    #pragma unroll 4
    for (int kk = 0; kk < 128; kk += 4) {
        float4 av[4];
        ulonglong2 wA[4], wB[4];
        #pragma unroll
        for (int r = 0; r < 4; r++) av[r] = *(const float4*)&As[(r0 + r) * 128 + kk];
        #pragma unroll
        for (int i = 0; i < 4; i++) {
            wA[i] = *(const ulonglong2*)&Ws[(kk + i) * 128 + cA];
            wB[i] = *(const ulonglong2*)&Ws[(kk + i) * 128 + cB];
        }
        #pragma unroll
        for (int r = 0; r < 4; r++) {
            ull ad;
            PACK2(ad, av[r].x);
            FMA2(acc[r][0], ad, wA[0].x); FMA2(acc[r][1], ad, wA[0].y);
            FMA2(acc[r][2], ad, wB[0].x); FMA2(acc[r][3], ad, wB[0].y);
            PACK2(ad, av[r].y);
            FMA2(acc[r][0], ad, wA[1].x); FMA2(acc[r][1], ad, wA[1].y);
            FMA2(acc[r][2], ad, wB[1].x); FMA2(acc[r][3], ad, wB[1].y);
            PACK2(ad, av[r].z);
            FMA2(acc[r][0], ad, wA[2].x); FMA2(acc[r][1], ad, wA[2].y);
            FMA2(acc[r][2], ad, wB[2].x); FMA2(acc[r][3], ad, wB[2].y);
            PACK2(ad, av[r].w);
            FMA2(acc[r][0], ad, wA[3].x); FMA2(acc[r][1], ad, wA[3].y);
            FMA2(acc[r][2], ad, wB[3].x); FMA2(acc[r][3], ad, wB[3].y);
        }
    }

    int colA = blockIdx.y * 128 + cA;
    int colB = blockIdx.y * 128 + cB;
    float4 bvA = *(const float4*)&bias[colA];
    float4 bvB = *(const float4*)&bias[colB];
    #pragma unroll
    for (int r = 0; r < 4; r++) {
        size_t rg = (size_t)blockIdx.x * 64 + r0 + r;
        float vA[4], vB[4];
        asm("mov.b64 {%0, %1}, %2;" : "=f"(vA[0]), "=f"(vA[1]) : "l"(acc[r][0]));
        asm("mov.b64 {%0, %1}, %2;" : "=f"(vA[2]), "=f"(vA[3]) : "l"(acc[r][1]));
        asm("mov.b64 {%0, %1}, %2;" : "=f"(vB[0]), "=f"(vB[1]) : "l"(acc[r][2]));
        asm("mov.b64 {%0, %1}, %2;" : "=f"(vB[2]), "=f"(vB[3]) : "l"(acc[r][3]));
        vA[0] += bvA.x; vA[1] += bvA.y; vA[2] += bvA.z; vA[3] += bvA.w;
        vB[0] += bvB.x; vB[1] += bvB.y; vB[2] += bvB.z; vB[3] += bvB.w;
        if (act == 1) {
            #pragma unroll
            for (int c = 0; c < 4; c++) { vA[c] = tanhfast(vA[c]); vB[c] = tanhfast(vB[c]); }
        } else if (act == 2) {
            #pragma unroll
            for (int c = 0; c < 4; c++) { vA[c] = sigf(vA[c]); vB[c] = sigf(vB[c]); }
        }
        *(float4*)&out[rg * N + colA] = make_float4(vA[0], vA[1], vA[2], vA[3]);
        *(float4*)&out[rg * N + colB] = make_float4(vB[0], vB[1], vB[2], vB[3]);
    }
}

// ---------------- recurrence: 16 clusters of 8 CTAs, 576 threads ----------
// Warp-specialized: threads 0..511 = GEMV (chunk wait -> GEMV -> STS ->
// bar.arrive -> next wait); threads 512..575 = dedicated elementwise (each
// handles 2 (row,unit) pairs; prefetch -> bar.sync -> LSTM -> stage -> bulk
// DSMEM copies). pb is parity double-buffered. Each ew warp copies ONLY the
// sub-chunks it wrote (rows {w, w+2}) -> __syncwarp is a sufficient guard.
__global__ void __launch_bounds__(576, 1) __cluster_dims__(8, 1, 1)
k_recur(const float* __restrict__ h0, const float* __restrict__ c0v,
        const float* __restrict__ Wh, const float* __restrict__ Wc) {
    __shared__ float hb0[1024];      // h buffer 0  [blk][row][32]
    __shared__ float hb1[1024];      // h buffer 1
    __shared__ float pb[2][4096];    // [parity][row(4)][ks(8)][col(128)]
    __shared__ float hstage[256];    // [phase(2)][row(4)][unit(32)]
    __shared__ ull   mbars[16];      // [chunk(8)][buf(2)]

    int tid   = threadIdx.x;
    int grp   = blockIdx.x >> 3;
    int cslot = blockIdx.x & 7;

    uint32_t mbar_a = s2u(mbars);
    uint32_t hb0_a  = s2u(hb0);
    uint32_t hb1_a  = s2u(hb1);
    uint32_t hst_a  = s2u(hstage);

    // h(0) into buffer 0, [blk][row][32] layout
    for (int i = tid; i < 1024; i += 576) {
        int blk = i >> 7, row = (i >> 5) & 3, u = i & 31;
        hb0[i] = h0[grp * 1024 + row * 256 + blk * 32 + u];
    }
    if (tid < 16) {
        uint32_t mb = mbar_a + (uint32_t)(tid * 8);
        asm volatile("mbarrier.init.shared.b64 [%0], %1;" :: "r"(mb), "r"(1) : "memory");
        asm volatile("mbarrier.arrive.expect_tx.shared.b64 _, [%0], %1;"
                     :: "r"(mb), "r"(512) : "memory");
    }
    __syncthreads();
    asm volatile("barrier.cluster.arrive.aligned;" ::: "memory");
    asm volatile("barrier.cluster.wait.aligned;"   ::: "memory");

    if (tid < 512) {
        // ================= GEMV warps =================
        int cpair = tid & 63;            // cols 2*cpair, 2*cpair+1
        int ks    = tid >> 6;            // K-slice / h-chunk
        int col0  = cpair * 2;
        int gq = col0 >> 5, gul = col0 & 31;
        int gcol = gq * 256 + cslot * 32 + gul;

        ull w2[2][16];
        #pragma unroll
        for (int c = 0; c < 2; c++) {
            const float* whp = Wh + gcol + c;
            #pragma unroll
            for (int i = 0; i < 16; i++) {
                int k = ks * 32 + 2 * i;
                float wlo = __ldg(whp + (size_t)k * 1024);
                float whi = __ldg(whp + (size_t)(k + 1) * 1024);
                asm("mov.b64 %0, {%1, %2};" : "=l"(w2[c][i]) : "f"(wlo), "f"(whi));
            }
        }

        unsigned par0 = 0, par1 = 0;
        for (int t = 0; t < 4096; t++) {
            int p = t & 1;
            const float* hb = p ? hb1 : hb0;
            if (t > 0) {
                uint32_t mb = mbar_a + (uint32_t)((ks * 2 + p) * 8);
                unsigned par = p ? par1 : par0;
                asm volatile(
                    "{\n\t.reg .pred P;\n\t"
                    "WL%=:\n\t"
                    "mbarrier.try_wait.parity.acquire.cta.shared::cta.b64 P, [%0], %1, 0x989680;\n\t"
                    "@P bra WD%=;\n\t"
                    "bra WL%=;\n\t"
                    "WD%=:\n\t}"
                    :: "r"(mb), "r"(par) : "memory");
                if (p) par1 ^= 1; else par0 ^= 1;
                if ((tid & 63) == 0)
                    asm volatile("mbarrier.arrive.expect_tx.shared.b64 _, [%0], %1;"
                                 :: "r"(mb), "r"(512) : "memory");
            }

            ull acc[4][2];
            #pragma unroll
            for (int r = 0; r < 4; r++) { acc[r][0] = 0ull; acc[r][1] = 0ull; }
            const float* base = hb + ks * 128;
            #pragma unroll
            for (int r = 0; r < 4; r++) {
                const ulonglong2* hp = (const ulonglong2*)(base + r * 32);
                #pragma unroll
                for (int i = 0; i < 8; i++) {
                    ulonglong2 hv = hp[i];
                    FMA2(acc[r][0], hv.x, w2[0][2 * i]);
                    FMA2(acc[r][1], hv.x, w2[1][2 * i]);
                    FMA2(acc[r][0], hv.y, w2[0][2 * i + 1]);
                    FMA2(acc[r][1], hv.y, w2[1][2 * i + 1]);
                }
            }
            float* pbp = pb[p];
            #pragma unroll
            for (int r = 0; r < 4; r++) {
                float lo, hi, s0, s1;
                asm("mov.b64 {%0, %1}, %2;" : "=f"(lo), "=f"(hi) : "l"(acc[r][0]));
                s0 = lo + hi;
                asm("mov.b64 {%0, %1}, %2;" : "=f"(lo), "=f"(hi) : "l"(acc[r][1]));
                s1 = lo + hi;
                ull pk;
                asm("mov.b64 %0, {%1, %2};" : "=l"(pk) : "f"(s0), "f"(s1));
                *(ull*)&pbp[r * 1024 + ks * 128 + col0] = pk;
            }
            asm volatile("bar.arrive 0, 576;" ::: "memory");
        }
    } else {
        // ================= elementwise warps (64 threads, 2 units each) ====
        int e = tid - 512;               // 0..63
        int ew = e >> 5;                 // ew warp id: 0 or 1
        int erA = ew;                    // row 0 or 1
        int erB = erA + 2;               // row 2 or 3
        int eul = e & 31;
        int egu = cslot * 32 + eul;

        float cA = c0v[(grp * 4 + erA) * 256 + egu];
        float cB = c0v[(grp * 4 + erB) * 256 + egu];
        float hA = h0[(grp * 4 + erA) * 256 + egu];
        float hB = h0[(grp * 4 + erB) * 256 + egu];
        float wc0 = Wc[egu], wc1 = Wc[256 + egu], wc2 = Wc[512 + egu];

        for (int t = 0; t < 4096; t++) {
            int p = t & 1;
            // prefetch both rows' xw (+bias baked) and j
            size_t xbA = ((size_t)(grp * 4 + erA) * 4096 + t) * 1024 + egu;
            size_t xbB = ((size_t)(grp * 4 + erB) * 4096 + t) * 1024 + egu;
            float a0 = __ldg(g_xw + xbA), a1 = __ldg(g_xw + xbA + 256);
            float a2 = __ldg(g_xw + xbA + 512), a3 = __ldg(g_xw + xbA + 768);
            float b0 = __ldg(g_xw + xbB), b1 = __ldg(g_xw + xbB + 256);
            float b2 = __ldg(g_xw + xbB + 512), b3 = __ldg(g_xw + xbB + 768);
            float jA = __ldg(g_j + ((size_t)(grp * 4 + erA) * 4096 + t) * 256 + egu);
            float jB = __ldg(g_j + ((size_t)(grp * 4 + erB) * 4096 + t) * 256 + egu);

            asm volatile("bar.sync 0, 576;" ::: "memory");

            const float* prA = pb[p] + erA * 1024;
            const float* prB = pb[p] + erB * 1024;
            #pragma unroll
            for (int q = 0; q < 8; q++) {
                a0 += prA[q * 128 +   0 + eul];
                a1 += prA[q * 128 +  32 + eul];
                a2 += prA[q * 128 +  64 + eul];
                a3 += prA[q * 128 +  96 + eul];
                b0 += prB[q * 128 +   0 + eul];
                b1 += prB[q * 128 +  32 + eul];
                b2 += prB[q * 128 +  64 + eul];
                b3 += prB[q * 128 +  96 + eul];
            }
            // LSTM updates (two independent rows, chains interleave)
            float ivA = sigf(a0 + cA * wc0), ivB = sigf(b0 + cB * wc0);
            float fvA = sigf(a1 + cA * wc1), fvB = sigf(b1 + cB * wc1);
            float gvA = tanhfast(a2),        gvB = tanhfast(b2);
            float ovA = sigf(a3 + cA * wc2), ovB = sigf(b3 + cB * wc2);
            float chA = fvA * cA + ivA * gvA;
            float chB = fvB * cB + ivB * gvB;
            float cnA = jA * chA + (1.f - jA) * cA;
            float cnB = jB * chB + (1.f - jB) * cB;
            float hhA = ovA * tanhfast(chA);
            float hhB = ovB * tanhfast(chB);
            float hnA = jA * hhA + (1.f - jA) * hA;
            float hnB = jB * hhB + (1.f - jB) * hB;
            cA = cnA; cB = cnB; hA = hnA; hB = hnB;

            if (t < 4095) {
                hstage[(1 - p) * 128 + erA * 32 + eul] = hnA;
                hstage[(1 - p) * 128 + erB * 32 + eul] = hnB;
                __syncwarp();
                asm volatile("fence.proxy.async.shared::cta;" ::: "memory");
                // each ew warp copies ONLY the sub-chunks it wrote:
                // warp ew owns rows {ew, ew+2} -> sub = ew + 2*(lane>>3)
                int lane = e & 31;
                if (lane < 16) {
                    int sub  = ew + ((lane >> 3) << 1);
                    int peer = lane & 7;
                    uint32_t src  = hst_a + (uint32_t)((1 - p) * 512 + sub * 128);
                    uint32_t dstl = (p ? hb0_a : hb1_a)
                                  + (uint32_t)(cslot * 512 + sub * 128);
                    uint32_t mbl  = mbar_a + (uint32_t)((cslot * 2 + (1 - p)) * 8);
                    uint32_t dst, mbr;
                    asm("mapa.shared::cluster.u32 %0, %1, %2;"
                        : "=r"(dst) : "r"(dstl), "r"(peer));
                    asm("mapa.shared::cluster.u32 %0, %1, %2;"
                        : "=r"(mbr) : "r"(mbl), "r"(peer));
                    asm volatile(
                        "cp.async.bulk.shared::cluster.shared::cta.mbarrier::complete_tx::bytes "
                        "[%0], [%1], %2, [%3];"
                        :: "r"(dst), "r"(src), "r"(128), "r"(mbr) : "memory");
                }
            } else {
                g_h[(grp * 4 + erA) * 256 + egu] = hnA;
                g_h[(grp * 4 + erB) * 256 + egu] = hnB;
            }
        }
    }

    asm volatile("barrier.cluster.arrive.aligned;" ::: "memory");
    asm volatile("barrier.cluster.wait.aligned;"   ::: "memory");
}

// ---------------- final: out = h_T @ Wlin + blin ----------------
__global__ void k_final(const float* __restrict__ Wlin,
                        const float* __restrict__ blin, float* __restrict__ out) {
    __shared__ float hsm[256];
    int b = blockIdx.x, d = threadIdx.x;   // 64 threads
    for (int i = d; i < 256; i += 64) hsm[i] = g_h[b * 256 + i];
    __syncthreads();
    float acc = blin[d];
    #pragma unroll 8
    for (int k = 0; k < 256; k++) acc += hsm[k] * Wlin[k * 64 + d];
    out[b * 64 + d] = acc;
}

// ---------------- launcher ----------------
extern "C" void kernel_launch(void* const* d_in, const int* in_sizes, int n_in,
                              void* d_out, int out_size) {
    (void)in_sizes; (void)n_in; (void)out_size;
    const float* ev   = (const float*)d_in[0];
    const float* vc   = (const float*)d_in[2];
    const float* vn   = (const float*)d_in[3];
    const float* h0   = (const float*)d_in[4];
    const float* c0   = (const float*)d_in[5];
    const float* Wx   = (const float*)d_in[6];
    const float* Wh   = (const float*)d_in[7];
    const float* Wc   = (const float*)d_in[8];
    const float* bias = (const float*)d_in[9];
    const float* Ve   = (const float*)d_in[10];
    const float* Vc   = (const float*)d_in[11];
    const float* Vn   = (const float*)d_in[12];
    const float* Wlin = (const float*)d_in[13];
    const float* blin = (const float*)d_in[14];
    const float* Wef1 = (const float*)d_in[15];
    const float* bef1 = (const float*)d_in[16];
    const float* Wef3 = (const float*)d_in[17];
    const float* bef3 = (const float*)d_in[18];
    float* out = (float*)d_out;

    cudaFuncSetAttribute(k_embed_u, cudaFuncAttributeMaxDynamicSharedMemorySize, 96256);
    cudaFuncSetAttribute(k_gemm,    cudaFuncAttributeMaxDynamicSharedMemorySize, 98304);

    void *px, *pu, *pxw, *pj;
    cudaGetSymbolAddress(&px,  g_x);
    cudaGetSymbolAddress(&pu,  g_u);
    cudaGetSymbolAddress(&pxw, g_xw);
    cudaGetSymbolAddress(&pj,  g_j);

    // 1: embeddings + u (fused)
    k_embed_u<<<MROWS / 32, 256, 96256>>>(ev, vc, vn, Ve, Vc, Vn, Wef1, bef1);
    // 2: xW = x @ Wx + bias            [M,1024]
    k_gemm<<<dim3(MROWS / 64, 8), 256, 98304>>>((const float*)px, Wx, bias,
                                                (float*)pxw, 1024, 0);
    // 3: j = sigmoid(u @ Wef3 + bef3)  [M,256]
    k_gemm<<<dim3(MROWS / 64, 2), 256, 98304>>>((const float*)pu, Wef3, bef3,
                                                (float*)pj, 256, 2);
    // 4: recurrence (target of ncu capture)
    k_recur<<<128, 576>>>(h0, c0, Wh, Wc);
    // 5: output projection
    k_final<<<64, 64>>>(Wlin, blin, out);
}

// round 13
// speedup vs baseline: 1.1554x; 1.1554x over previous
#include <cuda_runtime.h>
#include <cuda_bf16.h>
#include <cstdint>
#include <math.h>

#define S_LEN 4096
#define BATCH 64
#define HSZ   256
#define MROWS (BATCH * S_LEN)   // 262144

typedef unsigned long long ull;

// ---------------- device scratch (allocation-free rule) ----------------
__device__ float g_x [(size_t)MROWS * 128];           // x
__device__ float g_u [(size_t)MROWS * 128];           // tanh(s@Wef1+bef1)
__device__ float g_xw[(size_t)MROWS * 1024];          // [b][s][4HS] (bias baked in)
__device__ float g_j [(size_t)MROWS * HSZ];           // [b][s][HS]
__device__ float g_h [BATCH * HSZ];                   // final h

// fast activations: MUFU-based, saturate correctly at +-inf
__device__ __forceinline__ float sigf(float x) {
    return __fdividef(1.0f, 1.0f + __expf(-x));
}
__device__ __forceinline__ float tanhfast(float x) {
    return 1.0f - __fdividef(2.0f, __expf(2.0f * x) + 1.0f);
}

__device__ __forceinline__ uint32_t s2u(const void* p) {
    uint32_t r;
    asm("{ .reg .u64 t; cvta.to.shared.u64 t, %1; cvt.u32.u64 %0, t; }"
        : "=r"(r) : "l"(p));
    return r;
}

#define FMA2(d, a, b) \
    asm("fma.rn.f32x2 %0, %1, %2, %0;" : "+l"(d) : "l"(a), "l"(b))
#define PACK2(d, a) \
    asm("mov.b64 %0, {%1, %1};" : "=l"(d) : "f"(a))

// ---------------- fused embeddings + event-filter stage 1 ------------------
// s = ev@Ve ; x = s + 2*(vc@Vc + tanh(vn@Vn)) ; u = tanh(s@Wef1 + bef1)
__global__ void __launch_bounds__(256, 1)
k_embed_u(const float* __restrict__ ev, const float* __restrict__ vc,
          const float* __restrict__ vn, const float* __restrict__ Ve,
          const float* __restrict__ Vc, const float* __restrict__ Vn,
          const float* __restrict__ Wef1, const float* __restrict__ bef1) {
    extern __shared__ float sm[];
    float* wE  = sm;                 // [64][128]  -> Wef1 later
    float* wC  = sm + 8192;          // [32][128]
    float* wN  = sm + 12288;         // [16][128]
    float* ie  = sm + 16384;         // [32][64]
    float* ic  = ie + 2048;          // [32][32]
    float* inn = ic + 1024;          // [32][16]
    float* st  = sm + 19968;         // s-tile [32][128]
    int tid = threadIdx.x;
    size_t rb = (size_t)blockIdx.x * 32;

    for (int i = tid; i < 2048; i += 256) ((float4*)wE)[i]  = ((const float4*)Ve)[i];
    for (int i = tid; i < 1024; i += 256) ((float4*)wC)[i]  = ((const float4*)Vc)[i];
    for (int i = tid; i < 512;  i += 256) ((float4*)wN)[i]  = ((const float4*)Vn)[i];
    for (int i = tid; i < 512;  i += 256) ((float4*)ie)[i]  = ((const float4*)(ev + rb * 64))[i];
    for (int i = tid; i < 256;  i += 256) ((float4*)ic)[i]  = ((const float4*)(vc + rb * 32))[i];
    for (int i = tid; i < 128;  i += 256) ((float4*)inn)[i] = ((const float4*)(vn + rb * 16))[i];
    __syncthreads();

    int ty = tid >> 4, tx = tid & 15;
    float sa[2][8], ta[2][8], xa[2][8];
    #pragma unroll
    for (int r = 0; r < 2; r++)
        #pragma unroll
        for (int j = 0; j < 8; j++) { sa[r][j] = 0.f; ta[r][j] = 0.f; }

    #pragma unroll 4
    for (int k = 0; k < 64; k++) {
        float a0 = ie[(ty * 2) * 64 + k], a1 = ie[(ty * 2 + 1) * 64 + k];
        const float* wr = wE + k * 128 + tx * 8;
        float4 w0 = *(const float4*)wr, w1 = *(const float4*)(wr + 4);
        float w[8] = {w0.x, w0.y, w0.z, w0.w, w1.x, w1.y, w1.z, w1.w};
        #pragma unroll
        for (int j = 0; j < 8; j++) { sa[0][j] += a0 * w[j]; sa[1][j] += a1 * w[j]; }
    }
    #pragma unroll 4
    for (int k = 0; k < 32; k++) {
        float a0 = ic[(ty * 2) * 32 + k], a1 = ic[(ty * 2 + 1) * 32 + k];
        const float* wr = wC + k * 128 + tx * 8;
        float4 w0 = *(const float4*)wr, w1 = *(const float4*)(wr + 4);
        float w[8] = {w0.x, w0.y, w0.z, w0.w, w1.x, w1.y, w1.z, w1.w};
        #pragma unroll
        for (int j = 0; j < 8; j++) { ta[0][j] += a0 * w[j]; ta[1][j] += a1 * w[j]; }
    }
    #pragma unroll
    for (int r = 0; r < 2; r++)
        #pragma unroll
        for (int j = 0; j < 8; j++) { xa[r][j] = 2.f * ta[r][j]; ta[r][j] = 0.f; }
    #pragma unroll 4
    for (int k = 0; k < 16; k++) {
        float a0 = inn[(ty * 2) * 16 + k], a1 = inn[(ty * 2 + 1) * 16 + k];
        const float* wr = wN + k * 128 + tx * 8;
        float4 w0 = *(const float4*)wr, w1 = *(const float4*)(wr + 4);
        float w[8] = {w0.x, w0.y, w0.z, w0.w, w1.x, w1.y, w1.z, w1.w};
        #pragma unroll
        for (int j = 0; j < 8; j++) { ta[0][j] += a0 * w[j]; ta[1][j] += a1 * w[j]; }
    }
    #pragma unroll
    for (int r = 0; r < 2; r++) {
        int row = ty * 2 + r;
        size_t grow = rb + row;
        float o[8];
        #pragma unroll
        for (int j = 0; j < 8; j++) o[j] = sa[r][j] + xa[r][j] + 2.f * tanhfast(ta[r][j]);
        float* xp = g_x + grow * 128 + tx * 8;
        *(float4*)xp       = make_float4(o[0], o[1], o[2], o[3]);
        *(float4*)(xp + 4) = make_float4(o[4], o[5], o[6], o[7]);
        float* sp = st + row * 128 + tx * 8;
        *(float4*)sp       = make_float4(sa[r][0], sa[r][1], sa[r][2], sa[r][3]);
        *(float4*)(sp + 4) = make_float4(sa[r][4], sa[r][5], sa[r][6], sa[r][7]);
    }
    __syncthreads();

    for (int i = tid; i < 4096; i += 256) ((float4*)wE)[i] = ((const float4*)Wef1)[i];
    __syncthreads();

    float ua[2][8];
    #pragma unroll
    for (int r = 0; r < 2; r++)
        #pragma unroll
        for (int j = 0; j < 8; j++) ua[r][j] = 0.f;
    #pragma unroll 4
    for (int k = 0; k < 128; k++) {
        float a0 = st[(ty * 2) * 128 + k], a1 = st[(ty * 2 + 1) * 128 + k];
        const float* wr = wE + k * 128 + tx * 8;
        float4 w0 = *(const float4*)wr, w1 = *(const float4*)(wr + 4);
        float w[8] = {w0.x, w0.y, w0.z, w0.w, w1.x, w1.y, w1.z, w1.w};
        #pragma unroll
        for (int j = 0; j < 8; j++) { ua[0][j] += a0 * w[j]; ua[1][j] += a1 * w[j]; }
    }
    float4 b0 = *(const float4*)&bef1[tx * 8];
    float4 b1 = *(const float4*)&bef1[tx * 8 + 4];
    float bb[8] = {b0.x, b0.y, b0.z, b0.w, b1.x, b1.y, b1.z, b1.w};
    #pragma unroll
    for (int r = 0; r < 2; r++) {
        size_t grow = rb + ty * 2 + r;
        float o[8];
        #pragma unroll
        for (int j = 0; j < 8; j++) o[j] = tanhfast(ua[r][j] + bb[j]);
        float* up = g_u + grow * 128 + tx * 8;
        *(float4*)up       = make_float4(o[0], o[1], o[2], o[3]);
        *(float4*)(up + 4) = make_float4(o[4], o[5], o[6], o[7]);
    }
}

// ---------------- K=128 GEMM, 64x128 tile (f32x2): out = act(A@W + b) ------
__global__ void __launch_bounds__(256)
k_gemm(const float* __restrict__ A, const float* __restrict__ W,
       const float* __restrict__ bias, float* __restrict__ out,
       int N, int act) {
    extern __shared__ float sm[];
    float* As = sm;            // [64][128]   32 KB
    float* Ws = sm + 8192;     // [128][128]  64 KB
    int tid = threadIdx.x;
    const float4* A4 = (const float4*)A;
    const float4* W4 = (const float4*)W;
    for (int i = tid; i < 2048; i += 256)
        ((float4*)As)[i] = A4[((size_t)blockIdx.x * 64 + (i >> 5)) * 32 + (i & 31)];
    for (int i = tid; i < 4096; i += 256)
        ((float4*)Ws)[i] = W4[(size_t)(i >> 5) * (N >> 2) + blockIdx.y * 32 + (i & 31)];
    __syncthreads();

    int ty = tid >> 4, tx = tid & 15;
    int r0 = ty * 4, cA = tx * 4, cB = 64 + tx * 4;
    ull acc[4][4];
    #pragma unroll
    for (int r = 0; r < 4; r++)
        #pragma unroll
        for (int c = 0; c < 4; c++) acc[r][c] = 0ull;

    #pragma unroll 4
    for (int kk = 0; kk < 128; kk += 4) {
        float4 av[4];
        ulonglong2 wA[4], wB[4];
        #pragma unroll
        for (int r = 0; r < 4; r++) av[r] = *(const float4*)&As[(r0 + r) * 128 + kk];
        #pragma unroll
        for (int i = 0; i < 4; i++) {
            wA[i] = *(const ulonglong2*)&Ws[(kk + i) * 128 + cA];
            wB[i] = *(const ulonglong2*)&Ws[(kk + i) * 128 + cB];
        }
        #pragma unroll
        for (int r = 0; r < 4; r++) {
            ull ad;
            PACK2(ad, av[r].x);
            FMA2(acc[r][0], ad, wA[0].x); FMA2(acc[r][1], ad, wA[0].y);
            FMA2(acc[r][2], ad, wB[0].x); FMA2(acc[r][3], ad, wB[0].y);
            PACK2(ad, av[r].y);
            FMA2(acc[r][0], ad, wA[1].x); FMA2(acc[r][1], ad, wA[1].y);
            FMA2(acc[r][2], ad, wB[1].x); FMA2(acc[r][3], ad, wB[1].y);
            PACK2(ad, av[r].z);
            FMA2(acc[r][0], ad, wA[2].x); FMA2(acc[r][1], ad, wA[2].y);
            FMA2(acc[r][2], ad, wB[2].x); FMA2(acc[r][3], ad, wB[2].y);
            PACK2(ad, av[r].w);
            FMA2(acc[r][0], ad, wA[3].x); FMA2(acc[r][1], ad, wA[3].y);
            FMA2(acc[r][2], ad, wB[3].x); FMA2(acc[r][3], ad, wB[3].y);
        }
    }

    int colA = blockIdx.y * 128 + cA;
    int colB = blockIdx.y * 128 + cB;
    float4 bvA = *(const float4*)&bias[colA];
    float4 bvB = *(const float4*)&bias[colB];
    #pragma unroll
    for (int r = 0; r < 4; r++) {
        size_t rg = (size_t)blockIdx.x * 64 + r0 + r;
        float vA[4], vB[4];
        asm("mov.b64 {%0, %1}, %2;" : "=f"(vA[0]), "=f"(vA[1]) : "l"(acc[r][0]));
        asm("mov.b64 {%0, %1}, %2;" : "=f"(vA[2]), "=f"(vA[3]) : "l"(acc[r][1]));
        asm("mov.b64 {%0, %1}, %2;" : "=f"(vB[0]), "=f"(vB[1]) : "l"(acc[r][2]));
        asm("mov.b64 {%0, %1}, %2;" : "=f"(vB[2]), "=f"(vB[3]) : "l"(acc[r][3]));
        vA[0] += bvA.x; vA[1] += bvA.y; vA[2] += bvA.z; vA[3] += bvA.w;
        vB[0] += bvB.x; vB[1] += bvB.y; vB[2] += bvB.z; vB[3] += bvB.w;
        if (act == 1) {
            #pragma unroll
            for (int c = 0; c < 4; c++) { vA[c] = tanhfast(vA[c]); vB[c] = tanhfast(vB[c]); }
        } else if (act == 2) {
            #pragma unroll
            for (int c = 0; c < 4; c++) { vA[c] = sigf(vA[c]); vB[c] = sigf(vB[c]); }
        }
        *(float4*)&out[rg * N + colA] = make_float4(vA[0], vA[1], vA[2], vA[3]);
        *(float4*)&out[rg * N + colB] = make_float4(vB[0], vB[1], vB[2], vB[3]);
    }
}

// ---------------- recurrence: 16 clusters of 8 CTAs, 512 threads ----------
// (round-10 structure — best measured — plus pb parity double-buffer)
// cluster g owns batch rows 4g..4g+3; rank c owns units 32c..32c+31 (4 gates)
// h buffers [block(8)][row(4)][unit(32)]. PER-CHUNK barriers: GEMV warp-group
// ks waits only on the 512B chunk it reads. hprev carried in registers.
// Comm: bulk DSMEM copies, 128B sub-chunk per elementwise warp per peer.
__global__ void __launch_bounds__(512, 1) __cluster_dims__(8, 1, 1)
k_recur(const float* __restrict__ h0, const float* __restrict__ c0,
        const float* __restrict__ Wh, const float* __restrict__ Wc) {
    __shared__ float hb0[1024];      // h buffer 0  [blk][row][32]
    __shared__ float hb1[1024];      // h buffer 1
    __shared__ float pb[2][4096];    // [parity][row(4)][ks(8)][col(128)]
    __shared__ float hstage[256];    // [phase(2)][row(4)][unit(32)]
    __shared__ ull   mbars[16];      // [chunk(8)][buf(2)]

    int tid   = threadIdx.x;
    int grp   = blockIdx.x >> 3;
    int cslot = blockIdx.x & 7;

    int cpair = tid & 63;            // column pair: cols 2*cpair, 2*cpair+1
    int ks    = tid >> 6;            // K-slice / h-chunk: K in [ks*32, ks*32+32)
    int col0  = cpair * 2;
    int gq = col0 >> 5, gul = col0 & 31;
    int gcol = gq * 256 + cslot * 32 + gul;   // global gate column (even)

    // Wh slice in registers: 2 cols x 16 f32x2 pairs over this K-slice
    ull w2[2][16];
    #pragma unroll
    for (int c = 0; c < 2; c++) {
        const float* whp = Wh + gcol + c;
        #pragma unroll
        for (int i = 0; i < 16; i++) {
            int k = ks * 32 + 2 * i;
            float wlo = __ldg(whp + (size_t)k * 1024);
            float whi = __ldg(whp + (size_t)(k + 1) * 1024);
            asm("mov.b64 %0, {%1, %2};" : "=l"(w2[c][i]) : "f"(wlo), "f"(whi));
        }
    }

    // h(0) into buffer 0, [blk][row][32] layout
    for (int i = tid; i < 1024; i += 512) {
        int blk = i >> 7, row = (i >> 5) & 3, u = i & 31;
        hb0[i] = h0[grp * 1024 + row * 256 + blk * 32 + u];
    }

    uint32_t mbar_a = s2u(mbars);
    uint32_t hb0_a  = s2u(hb0);
    uint32_t hb1_a  = s2u(hb1);
    uint32_t hst_a  = s2u(hstage);
    if (tid < 16) {
        uint32_t mb = mbar_a + (uint32_t)(tid * 8);
        asm volatile("mbarrier.init.shared.b64 [%0], %1;" :: "r"(mb), "r"(1) : "memory");
        asm volatile("mbarrier.arrive.expect_tx.shared.b64 _, [%0], %1;"
                     :: "r"(mb), "r"(512) : "memory");
    }
    __syncthreads();
    asm volatile("barrier.cluster.arrive.aligned;" ::: "memory");
    asm volatile("barrier.cluster.wait.aligned;"   ::: "memory");

    int erow = tid >> 5, eul = tid & 31;      // elementwise role (tid < 128)
    int egu  = cslot * 32 + eul;              // global unit index
    float c_st = 0.f, h_pv = 0.f, wc0 = 0.f, wc1 = 0.f, wc2 = 0.f;
    if (tid < 128) {
        c_st = c0[(grp * 4 + erow) * 256 + egu];
        h_pv = h0[(grp * 4 + erow) * 256 + egu];   // hprev carried in register
        wc0 = Wc[egu]; wc1 = Wc[256 + egu]; wc2 = Wc[512 + egu];
    }

    unsigned par0 = 0, par1 = 0;
    for (int t = 0; t < 4096; t++) {
        int p = t & 1;
        const float* hb = p ? hb1 : hb0;

        // prefetch xw (+bias baked in, 4 gates) and j (hides under wait+GEMV)
        float xw0 = 0.f, xw1 = 0.f, xw2 = 0.f, xw3 = 0.f, jv = 0.f;
        if (tid < 128) {
            size_t xb = ((size_t)(grp * 4 + erow) * 4096 + t) * 1024 + egu;
            xw0 = __ldg(g_xw + xb);
            xw1 = __ldg(g_xw + xb + 256);
            xw2 = __ldg(g_xw + xb + 512);
            xw3 = __ldg(g_xw + xb + 768);
            jv  = __ldg(g_j + ((size_t)(grp * 4 + erow) * 4096 + t) * 256 + egu);
        }

        // wait ONLY for this warp-group's h chunk (skip t=0: preloaded)
        if (t > 0) {
            uint32_t mb = mbar_a + (uint32_t)((ks * 2 + p) * 8);
            unsigned par = p ? par1 : par0;
            asm volatile(
                "{\n\t.reg .pred P;\n\t"
                "WL%=:\n\t"
                "mbarrier.try_wait.parity.acquire.cta.shared::cta.b64 P, [%0], %1, 0x989680;\n\t"
                "@P bra WD%=;\n\t"
                "bra WL%=;\n\t"
                "WD%=:\n\t}"
                :: "r"(mb), "r"(par) : "memory");
            if (p) par1 ^= 1; else par0 ^= 1;
            if ((tid & 63) == 0)   // re-arm this chunk barrier for its next use
                asm volatile("mbarrier.arrive.expect_tx.shared.b64 _, [%0], %1;"
                             :: "r"(mb), "r"(512) : "memory");
        }

        // GEMV: LDS.128 h broadcasts, each reused for 2 cols x 2 pairs
        ull acc[4][2];
        #pragma unroll
        for (int r = 0; r < 4; r++) { acc[r][0] = 0ull; acc[r][1] = 0ull; }
        const float* base = hb + ks * 128;
        #pragma unroll
        for (int r = 0; r < 4; r++) {
            const ulonglong2* hp = (const ulonglong2*)(base + r * 32);
            #pragma unroll
            for (int i = 0; i < 8; i++) {
                ulonglong2 hv = hp[i];   // pairs (k, k+1), (k+2, k+3)
                FMA2(acc[r][0], hv.x, w2[0][2 * i]);
                FMA2(acc[r][1], hv.x, w2[1][2 * i]);
                FMA2(acc[r][0], hv.y, w2[0][2 * i + 1]);
                FMA2(acc[r][1], hv.y, w2[1][2 * i + 1]);
            }
        }
        // reduce pairs, store per-(row,ks) partials for 2 adjacent cols
        float* pbp = pb[p];
        #pragma unroll
        for (int r = 0; r < 4; r++) {
            float lo, hi, s0, s1;
            asm("mov.b64 {%0, %1}, %2;" : "=f"(lo), "=f"(hi) : "l"(acc[r][0]));
            s0 = lo + hi;
            asm("mov.b64 {%0, %1}, %2;" : "=f"(lo), "=f"(hi) : "l"(acc[r][1]));
            s1 = lo + hi;
            ull pk;
            asm("mov.b64 %0, {%1, %2};" : "=l"(pk) : "f"(s0), "f"(s1));
            *(ull*)&pbp[r * 1024 + ks * 128 + col0] = pk;
        }

        if (tid >= 128) {
            // GEMV-only warps: post arrival, head straight to next chunk wait
            asm volatile("bar.arrive 0, 512;" ::: "memory");
        } else {
            asm volatile("bar.sync 0, 512;" ::: "memory");
            // elementwise LSTM update (threads 0..127)
            const float* pr = pbp + erow * 1024;
            float G0 = xw0, G1 = xw1, G2 = xw2, G3 = xw3;
            #pragma unroll
            for (int q = 0; q < 8; q++) {
                G0 += pr[q * 128 +   0 + eul];
                G1 += pr[q * 128 +  32 + eul];
                G2 += pr[q * 128 +  64 + eul];
                G3 += pr[q * 128 +  96 + eul];
            }
            float cc = c_st;
            float iv = sigf(G0 + cc * wc0);
            float fv = sigf(G1 + cc * wc1);
            float gv = tanhfast(G2);
            float ov = sigf(G3 + cc * wc2);
            float chat = fv * cc + iv * gv;
            float cn = jv * chat + (1.f - jv) * cc;
            float hh = ov * tanhfast(chat);
            float hn = jv * hh + (1.f - jv) * h_pv;
            c_st = cn;
            h_pv = hn;
            if (t < 4095) {
                // stage this warp's 32 h values; lanes 0..7 each push the
                // 128B sub-chunk to one peer CTA (barrier of chunk cslot)
                hstage[(1 - p) * 128 + tid] = hn;
                __syncwarp();
                asm volatile("fence.proxy.async.shared::cta;" ::: "memory");
                int w = tid >> 5, lane = tid & 31;
                if (lane < 8) {
                    uint32_t src  = hst_a + (uint32_t)((1 - p) * 512 + w * 128);
                    uint32_t dstl = (p ? hb0_a : hb1_a)
                                  + (uint32_t)(cslot * 512 + w * 128);
                    uint32_t mbl  = mbar_a + (uint32_t)((cslot * 2 + (1 - p)) * 8);
                    uint32_t dst, mbr;
                    asm("mapa.shared::cluster.u32 %0, %1, %2;"
                        : "=r"(dst) : "r"(dstl), "r"(lane));
                    asm("mapa.shared::cluster.u32 %0, %1, %2;"
                        : "=r"(mbr) : "r"(mbl), "r"(lane));
                    asm volatile(
                        "cp.async.bulk.shared::cluster.shared::cta.mbarrier::complete_tx::bytes "
                        "[%0], [%1], %2, [%3];"
                        :: "r"(dst), "r"(src), "r"(128), "r"(mbr) : "memory");
                }
            } else {
                g_h[(grp * 4 + erow) * 256 + egu] = hn;
            }
        }
    }

    asm volatile("barrier.cluster.arrive.aligned;" ::: "memory");
    asm volatile("barrier.cluster.wait.aligned;"   ::: "memory");
}

// ---------------- final: out = h_T @ Wlin + blin ----------------
__global__ void k_final(const float* __restrict__ Wlin,
                        const float* __restrict__ blin, float* __restrict__ out) {
    __shared__ float hsm[256];
    int b = blockIdx.x, d = threadIdx.x;   // 64 threads
    for (int i = d; i < 256; i += 64) hsm[i] = g_h[b * 256 + i];
    __syncthreads();
    float acc = blin[d];
    #pragma unroll 8
    for (int k = 0; k < 256; k++) acc += hsm[k] * Wlin[k * 64 + d];
    out[b * 64 + d] = acc;
}

// ---------------- launcher ----------------
extern "C" void kernel_launch(void* const* d_in, const int* in_sizes, int n_in,
                              void* d_out, int out_size) {
    (void)in_sizes; (void)n_in; (void)out_size;
    const float* ev   = (const float*)d_in[0];
    const float* vc   = (const float*)d_in[2];
    const float* vn   = (const float*)d_in[3];
    const float* h0   = (const float*)d_in[4];
    const float* c0   = (const float*)d_in[5];
    const float* Wx   = (const float*)d_in[6];
    const float* Wh   = (const float*)d_in[7];
    const float* Wc   = (const float*)d_in[8];
    const float* bias = (const float*)d_in[9];
    const float* Ve   = (const float*)d_in[10];
    const float* Vc   = (const float*)d_in[11];
    const float* Vn   = (const float*)d_in[12];
    const float* Wlin = (const float*)d_in[13];
    const float* blin = (const float*)d_in[14];
    const float* Wef1 = (const float*)d_in[15];
    const float* bef1 = (const float*)d_in[16];
    const float* Wef3 = (const float*)d_in[17];
    const float* bef3 = (const float*)d_in[18];
    float* out = (float*)d_out;

    cudaFuncSetAttribute(k_embed_u, cudaFuncAttributeMaxDynamicSharedMemorySize, 96256);
    cudaFuncSetAttribute(k_gemm,    cudaFuncAttributeMaxDynamicSharedMemorySize, 98304);

    void *px, *pu, *pxw, *pj;
    cudaGetSymbolAddress(&px,  g_x);
    cudaGetSymbolAddress(&pu,  g_u);
    cudaGetSymbolAddress(&pxw, g_xw);
    cudaGetSymbolAddress(&pj,  g_j);

    // 1: embeddings + u (fused)
    k_embed_u<<<MROWS / 32, 256, 96256>>>(ev, vc, vn, Ve, Vc, Vn, Wef1, bef1);
    // 2: xW = x @ Wx + bias            [M,1024]
    k_gemm<<<dim3(MROWS / 64, 8), 256, 98304>>>((const float*)px, Wx, bias,
                                                (float*)pxw, 1024, 0);
    // 3: j = sigmoid(u @ Wef3 + bef3)  [M,256]
    k_gemm<<<dim3(MROWS / 64, 2), 256, 98304>>>((const float*)pu, Wef3, bef3,
                                                (float*)pj, 256, 2);
    // 4: recurrence (target of ncu capture)
    k_recur<<<128, 512>>>(h0, c0, Wh, Wc);
    // 5: output projection
    k_final<<<64, 64>>>(Wlin, blin, out);
}